// round 5
// baseline (speedup 1.0000x reference)
#include <cuda_runtime.h>
#include <stdint.h>

// Problem constants (fixed: IM_SIZE=(1080,1920), SCALE=(0.25,0.25), B=8, C=3)
#define H_IN 1080
#define W_IN 1920
#define OH   270
#define OW   480
#define BC   24
#define MAX_TAPS 20
#define WQ    (W_IN / 4)             // 480 float4 per row
#define R_OH  5                      // output rows per block (270 % 5 == 0)
#define SROW_SZ (W_IN + W_IN / 32)   // skewed row buffer: 1980 floats

// ---------------------------------------------------------------------------
// Fused bicubic resize: vertical accumulate (global, coalesced float4) ->
// skewed smem row -> horizontal gather (conflict-free LDS) -> output.
// grid: (1, OH/R_OH, BC), block: 480 (thread == ow == wq)
// ---------------------------------------------------------------------------
template <int TAPS>
__global__ void __launch_bounds__(480)
fused_resize(const float* __restrict__ x,
             const float* __restrict__ w_h,
             const int*   __restrict__ idx_h,
             const float* __restrict__ w_w,
             const int*   __restrict__ idx_w,
             float* __restrict__ out,
             int taps_h_rt, int taps_w_rt)
{
    const int th = (TAPS > 0) ? TAPS : taps_h_rt;
    const int tw = (TAPS > 0) ? TAPS : taps_w_rt;

    __shared__ float srow[SROW_SZ];
    __shared__ float swv[R_OH * MAX_TAPS];
    __shared__ int   srv[R_OH * MAX_TAPS];

    const int t   = threadIdx.x;          // == ow == wq
    const int bc  = blockIdx.z;
    const int oh0 = blockIdx.y * R_OH;

    // --- per-thread horizontal tables (registerized, amortized over R_OH rows)
    float wreg[(TAPS > 0) ? TAPS : MAX_TAPS];
    int   preg[(TAPS > 0) ? TAPS : MAX_TAPS];
#pragma unroll
    for (int p = 0; p < ((TAPS > 0) ? TAPS : MAX_TAPS); ++p) {
        if (TAPS == 0 && p >= tw) break;
        wreg[p] = w_w[t * tw + p];
        int c = idx_w[t * tw + p];
        c = (c < 0) ? 0 : (c > W_IN - 1 ? W_IN - 1 : c);
        preg[p] = c + (c >> 5);           // skewed position
    }

    // --- stage vertical weights/rows for all R_OH output rows of this block
    for (int i = t; i < R_OH * th; i += 480) {
        const int r  = i / th;
        const int p  = i - r * th;
        const int oh = oh0 + r;
        if (oh < OH) {
            swv[i] = w_h[oh * th + p];
            int rr = idx_h[oh * th + p];
            rr = (rr < 0) ? 0 : (rr > H_IN - 1 ? H_IN - 1 : rr);
            srv[i] = rr;
        }
    }
    __syncthreads();

    const int c0   = t * 4;
    const int base = c0 + (c0 >> 5);      // 4 floats stay within one 32-group
    const float4* xbase = (const float4*)x + (size_t)bc * H_IN * WQ + t;

    for (int r = 0; r < R_OH; ++r) {
        const int oh = oh0 + r;
        if (oh >= OH) break;              // uniform across block

        // vertical resample for this thread's float4 column
        float4 acc = make_float4(0.f, 0.f, 0.f, 0.f);
#pragma unroll
        for (int p = 0; p < ((TAPS > 0) ? TAPS : MAX_TAPS); ++p) {
            if (TAPS == 0 && p >= th) break;
            const float  w = swv[r * th + p];
            const float4 v = __ldg(xbase + (size_t)srv[r * th + p] * WQ);
            acc.x += w * v.x; acc.y += w * v.y; acc.z += w * v.z; acc.w += w * v.w;
        }

        __syncthreads();                  // prev iteration's gathers done
        srow[base + 0] = acc.x;
        srow[base + 1] = acc.y;
        srow[base + 2] = acc.z;
        srow[base + 3] = acc.w;
        __syncthreads();

        // horizontal gather (conflict-free via skew) -> coalesced store
        float o = 0.f;
#pragma unroll
        for (int p = 0; p < ((TAPS > 0) ? TAPS : MAX_TAPS); ++p) {
            if (TAPS == 0 && p >= tw) break;
            o += wreg[p] * srow[preg[p]];
        }
        out[((size_t)bc * OH + oh) * OW + t] = o;
    }
}

// ---------------------------------------------------------------------------
// kernel_launch
// inputs: x(f32), w_h(f32), idx_h(i32), w_w(f32), idx_w(i32); output f32
// ---------------------------------------------------------------------------
extern "C" void kernel_launch(void* const* d_in, const int* in_sizes, int n_in,
                              void* d_out, int out_size)
{
    const float* x     = (const float*)d_in[0];
    const float* w_h   = (const float*)d_in[1];
    const int*   idx_h = (const int*)d_in[2];
    const float* w_w   = (const float*)d_in[3];
    const int*   idx_w = (const int*)d_in[4];
    float*       out   = (float*)d_out;

    int taps_h = in_sizes[1] / OH;
    int taps_w = in_sizes[3] / OW;
    if (taps_h > MAX_TAPS) taps_h = MAX_TAPS;
    if (taps_w > MAX_TAPS) taps_w = MAX_TAPS;

    dim3 grid(1, (OH + R_OH - 1) / R_OH, BC);   // (1, 54, 24)
    if (taps_h == 16 && taps_w == 16)
        fused_resize<16><<<grid, 480>>>(x, w_h, idx_h, w_w, idx_w, out, taps_h, taps_w);
    else
        fused_resize<0><<<grid, 480>>>(x, w_h, idx_h, w_w, idx_w, out, taps_h, taps_w);
}